// round 6
// baseline (speedup 1.0000x reference)
#include <cuda_runtime.h>
#include <cuda_fp16.h>
#include <math.h>
#include <stdint.h>

#define NTOK 32768   // B*T
#define DDIM 512
#define NEXP 8
#define FDIM 2048
#define CAP  4096

#define BM 128
#define BN 256
#define BK 64
#define STAGES 3
#define STAGE_BYTES 49152          // A 16K | B 32K  (fp16)
#define DYN_SMEM (STAGES * STAGE_BYTES + 1024)
#define XPREP_SMEM 92160

// ---------------- device scratch (static; no allocations allowed) -----------
__device__ __align__(128) float g_logitsT[NEXP * NTOK];          // [E][N]
__device__ float g_colmax[NEXP];
__device__ float g_colsum[NEXP];
__device__ __align__(128) int   g_idx [NEXP * CAP];
__device__ __align__(128) float g_vals[NEXP * CAP];
__device__ __align__(128) int   g_tokcnt[NTOK];
__device__ __align__(128) int   g_toklist[NTOK * 8];             // (e*CAP+slot) refs
__device__ __align__(128) __half g_xh [(size_t)NTOK * DDIM];
__device__ __align__(128) __half g_w1h[(size_t)NEXP * FDIM * DDIM]; // W1^T [E][F][D]
__device__ __align__(128) __half g_w2h[(size_t)NEXP * DDIM * FDIM]; // W2^T [E][D][F]
__device__ __align__(128) __half g_hh [(size_t)NEXP * CAP * FDIM];  // h [E][C][F]
__device__ __align__(128) float g_oute[(size_t)NEXP * CAP * DDIM];  // weighted expert out

// ---------------- small helpers ---------------------------------------------
__device__ __forceinline__ unsigned f2k(float f) {
    unsigned u = __float_as_uint(f);
    return u ^ ((u & 0x80000000u) ? 0xFFFFFFFFu : 0x80000000u);
}
__device__ __forceinline__ float gelu_exact(float v) {
    return 0.5f * v * (1.0f + erff(v * 0.70710678118654752440f));
}
__device__ __forceinline__ uint32_t cvta_smem(const void* p) {
    uint32_t a;
    asm("{ .reg .u64 t; cvta.to.shared.u64 t, %1; cvt.u32.u64 %0, t; }" : "=r"(a) : "l"(p));
    return a;
}
// SW128 swizzle for 128-byte rows: XOR 16B-unit bits [6:4] with row bits [9:7]
__device__ __forceinline__ uint32_t swz128(uint32_t o) { return o ^ ((o >> 3) & 0x70); }
__device__ __forceinline__ uint32_t packh(__half a, __half b) {
    return (uint32_t)__half_as_ushort(a) | ((uint32_t)__half_as_ushort(b) << 16);
}

#define CP16(dst, src) asm volatile("cp.async.cg.shared.global [%0], [%1], 16;" :: "r"(dst), "l"(src))
#define CP_COMMIT()    asm volatile("cp.async.commit_group;" ::: "memory")
#define CP_WAIT(n)     asm volatile("cp.async.wait_group %0;" :: "n"(n) : "memory")

__device__ __forceinline__ void ldsm4(uint32_t* r, uint32_t addr) {
    asm volatile("ldmatrix.sync.aligned.m8n8.x4.shared.b16 {%0,%1,%2,%3}, [%4];"
                 : "=r"(r[0]), "=r"(r[1]), "=r"(r[2]), "=r"(r[3]) : "r"(addr));
}
__device__ __forceinline__ void mma16816(float* c, const uint32_t* a, const uint32_t* b) {
    asm volatile(
        "mma.sync.aligned.m16n8k16.row.col.f32.f16.f16.f32 "
        "{%0,%1,%2,%3}, {%4,%5,%6,%7}, {%8,%9}, {%0,%1,%2,%3};"
        : "+f"(c[0]), "+f"(c[1]), "+f"(c[2]), "+f"(c[3])
        : "r"(a[0]), "r"(a[1]), "r"(a[2]), "r"(a[3]), "r"(b[0]), "r"(b[1]));
}

// ---------------- K1: fused x->fp16 convert + router logits -----------------
// Block: 256 threads, 32 tokens. lane = token; warp w owns dims [w*64, w*64+64).
// fp32 logits in registers, no shuffles; W read as smem broadcasts.
__global__ __launch_bounds__(256, 2) void k_xprep(const float* __restrict__ x,
                                                  const float* __restrict__ Wr)
{
    extern __shared__ __align__(16) float dynf[];
    float* sx = dynf;                         // [32][516]
    float* sW = dynf + 32 * 516;              // [8][512]
    float* sp = sW + NEXP * 512;              // [8][32][8]

    const int tid = threadIdx.x, warp = tid >> 5, lane = tid & 31;
    const int t0 = blockIdx.x * 32;

    if (tid < 32) g_tokcnt[t0 + tid] = 0;
    for (int i = tid; i < 4096; i += 256) {   // W: [d][e] -> sW[e][d]
        int d = i >> 3, e = i & 7;
        sW[e * 512 + d] = Wr[d * NEXP + e];
    }
    for (int i = tid; i < 4096; i += 256) {   // 32 tok x 128 float4
        int tok = i >> 7, dd = (i & 127) * 4;
        float4 v = *(const float4*)(x + (size_t)(t0 + tok) * DDIM + dd);
        *(float4*)&sx[tok * 516 + dd] = v;
        uint2 p;
        p.x = packh(__float2half(v.x), __float2half(v.y));
        p.y = packh(__float2half(v.z), __float2half(v.w));
        ((uint2*)g_xh)[((size_t)(t0 + tok) * DDIM + dd) >> 2] = p;
    }
    __syncthreads();

    float acc[NEXP] = {};
    const int d0 = warp * 64;
#pragma unroll
    for (int i = 0; i < 16; i++) {
        float4 xv = *(const float4*)&sx[lane * 516 + d0 + i * 4];
#pragma unroll
        for (int e = 0; e < NEXP; e++) {
            float4 w = *(const float4*)&sW[e * 512 + d0 + i * 4];  // broadcast
            acc[e] += xv.x * w.x + xv.y * w.y + xv.z * w.z + xv.w * w.w;
        }
    }
#pragma unroll
    for (int e = 0; e < NEXP; e++)
        sp[(warp * 32 + lane) * NEXP + e] = acc[e];
    __syncthreads();

    int tok = tid >> 3, e = tid & 7;
    float s = 0.f;
#pragma unroll
    for (int w = 0; w < 8; w++) s += sp[(w * 32 + tok) * NEXP + e];
    g_logitsT[e * NTOK + t0 + tok] = s;
}

// ---------------- K2: per-expert column max + sum(exp) ----------------------
__global__ void k_colstats()
{
    int e = blockIdx.x;
    const float* col = g_logitsT + e * NTOK;
    __shared__ float red[512];
    int tid = threadIdx.x;
    float mx = -INFINITY;
    for (int n = tid; n < NTOK; n += 512) mx = fmaxf(mx, col[n]);
    red[tid] = mx; __syncthreads();
    for (int s = 256; s > 0; s >>= 1) {
        if (tid < s) red[tid] = fmaxf(red[tid], red[tid + s]);
        __syncthreads();
    }
    mx = red[0]; __syncthreads();
    float sm = 0.f;
    for (int n = tid; n < NTOK; n += 512) sm += expf(col[n] - mx);
    red[tid] = sm; __syncthreads();
    for (int s = 256; s > 0; s >>= 1) {
        if (tid < s) red[tid] += red[tid + s];
        __syncthreads();
    }
    if (tid == 0) { g_colmax[e] = mx; g_colsum[e] = red[0]; }
}

// ---------------- K3: per-expert exact top-CAP via 8-bit histogram radix ----
__global__ void k_select()
{
    int e = blockIdx.x;
    const float* col = g_logitsT + e * NTOK;
    __shared__ int s_hist[256];
    __shared__ unsigned s_prefix;
    __shared__ int s_need, s_pos;
    __shared__ int s_eq[1024];
    int tid = threadIdx.x;
    if (tid == 0) { s_prefix = 0u; s_need = CAP; s_pos = 0; }

#pragma unroll
    for (int shift = 24; shift >= 0; shift -= 8) {
        if (tid < 256) s_hist[tid] = 0;
        __syncthreads();
        unsigned pref = s_prefix;
        unsigned maskH = (shift == 24) ? 0u : (0xFFFFFFFFu << (shift + 8));
        for (int n = tid; n < NTOK; n += 1024) {
            unsigned k = f2k(col[n]);
            if ((k & maskH) == pref)
                atomicAdd(&s_hist[(k >> shift) & 255], 1);
        }
        __syncthreads();
        if (tid == 0) {
            int need = s_need, cum = 0, b = 255;
            for (; b > 0; b--) { cum += s_hist[b]; if (cum >= need) break; }
            if (cum < need) cum += s_hist[0];
            s_need = need - (cum - s_hist[b]);
            s_prefix = pref | ((unsigned)b << shift);
        }
        __syncthreads();
    }
    unsigned thr = s_prefix;
    int needEq = s_need;
    float mx = g_colmax[e];
    float sm = g_colsum[e];

    for (int n = tid; n < NTOK; n += 1024) {
        float lv = col[n];
        if (f2k(lv) > thr) {
            int slot = atomicAdd(&s_pos, 1);
            g_idx [e * CAP + slot] = n;
            g_vals[e * CAP + slot] = expf(lv - mx) / sm;
            int p = atomicAdd(&g_tokcnt[n], 1);
            g_toklist[n * 8 + p] = e * CAP + slot;
        }
    }
    __syncthreads();
    int G = s_pos;

    int n0 = tid * (NTOK / 1024);
    int cntEq = 0;
    for (int n = n0; n < n0 + NTOK / 1024; n++) cntEq += (f2k(col[n]) == thr);
    s_eq[tid] = cntEq;
    __syncthreads();
    for (int off = 1; off < 1024; off <<= 1) {
        int v = (tid >= off) ? s_eq[tid - off] : 0;
        __syncthreads();
        s_eq[tid] += v;
        __syncthreads();
    }
    int rank = s_eq[tid] - cntEq;
    for (int n = n0; n < n0 + NTOK / 1024; n++) {
        if (f2k(col[n]) == thr) {
            if (rank < needEq) {
                int slot = G + rank;
                g_idx [e * CAP + slot] = n;
                g_vals[e * CAP + slot] = expf(col[n] - mx) / sm;
                int p = atomicAdd(&g_tokcnt[n], 1);
                g_toklist[n * 8 + p] = e * CAP + slot;
            }
            rank++;
        }
    }
}

// ---------------- weight converts (transpose to K-major fp16) ---------------
__global__ void k_cvt_w1(const float* __restrict__ W1)
{
    __shared__ float t[32][33];
    const int R = DDIM, C = FDIM;
    int e = blockIdx.z;
    const float* S = W1 + (size_t)e * R * C;
    int c0 = blockIdx.x * 32, r0 = blockIdx.y * 32;
    int tx = threadIdx.x, ty = threadIdx.y;
#pragma unroll
    for (int i = 0; i < 4; i++)
        t[ty + 8 * i][tx] = S[(size_t)(r0 + ty + 8 * i) * C + c0 + tx];
    __syncthreads();
#pragma unroll
    for (int i = 0; i < 4; i++) {
        float v = t[tx][ty + 8 * i];
        size_t o = (size_t)e * C * R + (size_t)(c0 + ty + 8 * i) * R + r0 + tx;
        g_w1h[o] = __float2half(v);
    }
}

__global__ void k_cvt_w2(const float* __restrict__ W2)
{
    __shared__ float t[32][33];
    const int R = FDIM, C = DDIM;
    int e = blockIdx.z;
    const float* S = W2 + (size_t)e * R * C;
    int c0 = blockIdx.x * 32, r0 = blockIdx.y * 32;
    int tx = threadIdx.x, ty = threadIdx.y;
#pragma unroll
    for (int i = 0; i < 4; i++)
        t[ty + 8 * i][tx] = S[(size_t)(r0 + ty + 8 * i) * C + c0 + tx];
    __syncthreads();
#pragma unroll
    for (int i = 0; i < 4; i++) {
        float v = t[tx][ty + 8 * i];
        size_t o = (size_t)e * C * R + (size_t)(c0 + ty + 8 * i) * R + r0 + tx;
        g_w2h[o] = __float2half(v);
    }
}

// ================== mma.sync GEMM mainloop helpers ==========================
// 8 warps: mwarp = wid&1 (64 rows), nwarp = wid>>1 (64 cols). 64x64 warp tile.
struct FragState {
    uint32_t aoff[4][4];   // [mfrag][kk]
    uint32_t boff[4][4];   // [nf2][kk]
};
__device__ __forceinline__ void frag_offsets(FragState& fs, int lane, int mwarp, int nwarp)
{
    int r16 = lane & 15, hi16 = (lane >> 4) * 16;
#pragma unroll
    for (int mf = 0; mf < 4; mf++)
#pragma unroll
        for (int kk = 0; kk < 4; kk++)
            fs.aoff[mf][kk] = swz128((uint32_t)((mwarp * 64 + mf * 16 + r16) * 128 + kk * 32 + hi16));
#pragma unroll
    for (int nf2 = 0; nf2 < 4; nf2++)
#pragma unroll
        for (int kk = 0; kk < 4; kk++)
            fs.boff[nf2][kk] = swz128((uint32_t)((nwarp * 64 + nf2 * 16 + r16) * 128 + kk * 32 + hi16));
}

__device__ __forceinline__ void compute_stage(float c[4][8][4], const FragState& fs,
                                              uint32_t abase)
{
    const uint32_t bbase = abase + 16384;
#pragma unroll
    for (int kk = 0; kk < 4; kk++) {
        uint32_t a[4][4], b[8][2];
#pragma unroll
        for (int mf = 0; mf < 4; mf++)
            ldsm4(a[mf], abase + fs.aoff[mf][kk]);
#pragma unroll
        for (int nf2 = 0; nf2 < 4; nf2++) {
            uint32_t r[4];
            ldsm4(r, bbase + fs.boff[nf2][kk]);
            b[2 * nf2][0] = r[0]; b[2 * nf2][1] = r[2];
            b[2 * nf2 + 1][0] = r[1]; b[2 * nf2 + 1][1] = r[3];
        }
#pragma unroll
        for (int mf = 0; mf < 4; mf++)
#pragma unroll
            for (int nf = 0; nf < 8; nf++)
                mma16816(c[mf][nf], a[mf], b[nf]);
    }
}

// ---------------- GEMM1: h = gelu(gather(x) @ W1 + b1) ----------------------
__device__ __forceinline__ void g1_load(int tid, const int* s_tok, int e, int bn0,
                                        uint32_t dynb, int kt, int st)
{
    int k0 = kt * BK;
    uint32_t base = dynb + st * STAGE_BYTES;
#pragma unroll
    for (int t = tid; t < 1024; t += 256) {       // A: 128 rows x 128B
        int row = t >> 3, cc = t & 7;
        uint32_t o = swz128((uint32_t)(row * 128 + cc * 16));
        CP16(base + o, g_xh + (size_t)s_tok[row] * DDIM + k0 + cc * 8);
    }
#pragma unroll
    for (int t = tid; t < 2048; t += 256) {       // B: 256 rows x 128B
        int row = t >> 3, cc = t & 7;
        uint32_t o = swz128((uint32_t)(row * 128 + cc * 16));
        CP16(base + 16384 + o, g_w1h + (size_t)(e * FDIM + bn0 + row) * DDIM + k0 + cc * 8);
    }
}

__global__ __launch_bounds__(256, 1) void k_gemm1_mma(const float* __restrict__ b1)
{
    extern __shared__ __align__(16) unsigned char dynraw[];
    __shared__ int s_tok[BM];
    __shared__ float s_bias[BN];

    const int tid = threadIdx.x, wid = tid >> 5, lane = tid & 31;
    const int mwarp = wid & 1, nwarp = wid >> 1;
    const int e = blockIdx.z, bn0 = blockIdx.x * BN, bm0 = blockIdx.y * BM;

    uint32_t rawb = cvta_smem(dynraw);
    uint32_t pad = (1024u - (rawb & 1023u)) & 1023u;
    uint32_t dynb = rawb + pad;
    unsigned char* dynp = dynraw + pad;

    if (tid < BM) s_tok[tid] = g_idx[e * CAP + bm0 + tid];
    s_bias[tid] = b1[e * FDIM + bn0 + tid];
    __syncthreads();

    FragState fs;
    frag_offsets(fs, lane, mwarp, nwarp);
    float c[4][8][4] = {};

    const int KT = DDIM / BK;  // 8
    g1_load(tid, s_tok, e, bn0, dynb, 0, 0); CP_COMMIT();
    g1_load(tid, s_tok, e, bn0, dynb, 1, 1); CP_COMMIT();

    for (int kt = 0; kt < KT; kt++) {
        CP_WAIT(1);
        __syncthreads();
        if (kt + 2 < KT)
            g1_load(tid, s_tok, e, bn0, dynb, kt + 2, (kt + 2) % 3);
        CP_COMMIT();
        compute_stage(c, fs, dynb + (kt % 3) * STAGE_BYTES);
    }
    __syncthreads();   // done reading stages before epilogue reuses smem

    // epilogue: gelu -> fp16 -> smem stage (512B/row) -> coalesced 16B stores
#pragma unroll
    for (int mf = 0; mf < 4; mf++)
#pragma unroll
        for (int nf = 0; nf < 8; nf++)
#pragma unroll
            for (int half = 0; half < 2; half++) {
                int row = mwarp * 64 + mf * 16 + (lane >> 2) + half * 8;
                int col = nwarp * 64 + nf * 8 + (lane & 3) * 2;
                float v0 = c[mf][nf][half * 2 + 0] + s_bias[col];
                float v1 = c[mf][nf][half * 2 + 1] + s_bias[col + 1];
                uint32_t off = (uint32_t)row * 512 + (((uint32_t)col * 2) ^ (((uint32_t)row & 31) << 4));
                *(uint32_t*)(dynp + off) =
                    packh(__float2half(gelu_exact(v0)), __float2half(gelu_exact(v1)));
            }
    __syncthreads();
#pragma unroll
    for (int it = 0; it < 16; it++) {
        int g = tid + it * 256;                  // 4096 16B chunks (64KB)
        int r2 = g >> 5, seg = g & 31;
        uint32_t off = (uint32_t)r2 * 512 + (((uint32_t)seg * 16) ^ (((uint32_t)r2 & 31) << 4));
        uint4 vh = *(const uint4*)(dynp + off);
        size_t hb = ((size_t)(e * CAP + bm0 + r2)) * FDIM + bn0;
        *(uint4*)((char*)g_hh + hb * 2 + seg * 16) = vh;
    }
}

// ---------------- GEMM2: oute = (h @ W2 + b2) * vals ------------------------
__device__ __forceinline__ void g2_load(int tid, int e, int bn0, int bm0,
                                        uint32_t dynb, int kt, int st)
{
    int k0 = kt * BK;
    uint32_t base = dynb + st * STAGE_BYTES;
#pragma unroll
    for (int t = tid; t < 1024; t += 256) {
        int row = t >> 3, cc = t & 7;
        uint32_t o = swz128((uint32_t)(row * 128 + cc * 16));
        CP16(base + o, g_hh + (size_t)(e * CAP + bm0 + row) * FDIM + k0 + cc * 8);
    }
#pragma unroll
    for (int t = tid; t < 2048; t += 256) {
        int row = t >> 3, cc = t & 7;
        uint32_t o = swz128((uint32_t)(row * 128 + cc * 16));
        CP16(base + 16384 + o, g_w2h + (size_t)(e * DDIM + bn0 + row) * FDIM + k0 + cc * 8);
    }
}

__global__ __launch_bounds__(256, 1) void k_gemm2_mma(const float* __restrict__ b2)
{
    extern __shared__ __align__(16) unsigned char dynraw[];
    __shared__ float s_val[BM];
    __shared__ float s_bias[BN];

    const int tid = threadIdx.x, wid = tid >> 5, lane = tid & 31;
    const int mwarp = wid & 1, nwarp = wid >> 1;
    const int e = blockIdx.z, bn0 = blockIdx.x * BN, bm0 = blockIdx.y * BM;

    uint32_t rawb = cvta_smem(dynraw);
    uint32_t pad = (1024u - (rawb & 1023u)) & 1023u;
    uint32_t dynb = rawb + pad;
    unsigned char* dynp = dynraw + pad;

    if (tid < BM) s_val[tid] = g_vals[e * CAP + bm0 + tid];
    s_bias[tid] = b2[e * DDIM + bn0 + tid];
    __syncthreads();

    FragState fs;
    frag_offsets(fs, lane, mwarp, nwarp);
    float c[4][8][4] = {};

    const int KT = FDIM / BK;  // 32
    g2_load(tid, e, bn0, bm0, dynb, 0, 0); CP_COMMIT();
    g2_load(tid, e, bn0, bm0, dynb, 1, 1); CP_COMMIT();

    for (int kt = 0; kt < KT; kt++) {
        CP_WAIT(1);
        __syncthreads();
        if (kt + 2 < KT)
            g2_load(tid, e, bn0, bm0, dynb, kt + 2, (kt + 2) % 3);
        CP_COMMIT();
        compute_stage(c, fs, dynb + (kt % 3) * STAGE_BYTES);
    }
    __syncthreads();

    // epilogue: (acc + b2) * val -> f32 smem stage (1024B/row) -> 16B stores
#pragma unroll
    for (int mf = 0; mf < 4; mf++)
#pragma unroll
        for (int nf = 0; nf < 8; nf++)
#pragma unroll
            for (int half = 0; half < 2; half++) {
                int row = mwarp * 64 + mf * 16 + (lane >> 2) + half * 8;
                int col = nwarp * 64 + nf * 8 + (lane & 3) * 2;
                float vr = s_val[row];
                float2 o2;
                o2.x = (c[mf][nf][half * 2 + 0] + s_bias[col]) * vr;
                o2.y = (c[mf][nf][half * 2 + 1] + s_bias[col + 1]) * vr;
                uint32_t off = (uint32_t)row * 1024 + (((uint32_t)col * 4) ^ (((uint32_t)row & 63) << 4));
                *(float2*)(dynp + off) = o2;
            }
    __syncthreads();
#pragma unroll
    for (int it = 0; it < 32; it++) {
        int g = tid + it * 256;                  // 8192 16B chunks (128KB)
        int r2 = g >> 6, seg = g & 63;
        uint32_t off = (uint32_t)r2 * 1024 + (((uint32_t)seg * 16) ^ (((uint32_t)r2 & 63) << 4));
        uint4 v = *(const uint4*)(dynp + off);
        size_t ob = ((size_t)(e * CAP + bm0 + r2)) * DDIM + bn0;
        *(uint4*)((char*)g_oute + ob * 4 + seg * 16) = v;
    }
}

// ---------------- K6: gather-reduce scatter to output -----------------------
__global__ void k_scatter(float* __restrict__ out)
{
    int t = blockIdx.x * 2 + (threadIdx.x >> 7);
    int l = threadIdx.x & 127;
    int cnt = g_tokcnt[t];
    float4 acc = make_float4(0.f, 0.f, 0.f, 0.f);
    for (int i = 0; i < cnt; i++) {
        int ref = g_toklist[t * 8 + i];
        float4 v = ((const float4*)(g_oute + (size_t)ref * DDIM))[l];
        acc.x += v.x; acc.y += v.y; acc.z += v.z; acc.w += v.w;
    }
    ((float4*)out)[(size_t)t * (DDIM / 4) + l] = acc;
}

// ---------------------------------------------------------------------------
extern "C" void kernel_launch(void* const* d_in, const int* in_sizes, int n_in,
                              void* d_out, int out_size)
{
    const float* x  = (const float*)d_in[0];
    const float* Wr = (const float*)d_in[1];
    const float* W1 = (const float*)d_in[2];
    const float* b1 = (const float*)d_in[3];
    const float* W2 = (const float*)d_in[4];
    const float* b2 = (const float*)d_in[5];
    float* out = (float*)d_out;

    cudaFuncSetAttribute(k_xprep, cudaFuncAttributeMaxDynamicSharedMemorySize, XPREP_SMEM);
    cudaFuncSetAttribute(k_gemm1_mma, cudaFuncAttributeMaxDynamicSharedMemorySize, DYN_SMEM);
    cudaFuncSetAttribute(k_gemm2_mma, cudaFuncAttributeMaxDynamicSharedMemorySize, DYN_SMEM);

    k_xprep   <<<NTOK / 32, 256, XPREP_SMEM>>>(x, Wr);
    k_cvt_w1  <<<dim3(FDIM / 32, DDIM / 32, NEXP), dim3(32, 8)>>>(W1);
    k_cvt_w2  <<<dim3(DDIM / 32, FDIM / 32, NEXP), dim3(32, 8)>>>(W2);
    k_colstats<<<NEXP, 512>>>();
    k_select  <<<NEXP, 1024>>>();
    k_gemm1_mma<<<dim3(FDIM / BN, CAP / BM, NEXP), 256, DYN_SMEM>>>(b1);
    k_gemm2_mma<<<dim3(DDIM / BN, CAP / BM, NEXP), 256, DYN_SMEM>>>(b2);
    k_scatter <<<NTOK / 2, 256>>>(out);
}

// round 7
// speedup vs baseline: 1.1066x; 1.1066x over previous
#include <cuda_runtime.h>
#include <cuda_fp16.h>
#include <math.h>
#include <stdint.h>

#define NTOK 32768   // B*T
#define DDIM 512
#define NEXP 8
#define FDIM 2048
#define CAP  4096

#define BM 128
#define BN 128
#define BK 32
#define STAGES 4
#define STAGE_BYTES 16384          // A 8K | B 8K   (fp16)
#define DYN_SMEM (STAGES * STAGE_BYTES + 1024)
#define XPREP_SMEM 92160
#define NPART 8                    // colstats partials per expert

// ---------------- device scratch (static; no allocations allowed) -----------
__device__ __align__(128) float g_logitsT[NEXP * NTOK];          // [E][N]
__device__ float g_pmax[NEXP * NPART];
__device__ float g_psum[NEXP * NPART];
__device__ __align__(128) int   g_idx [NEXP * CAP];
__device__ __align__(128) float g_vals[NEXP * CAP];
__device__ __align__(128) int   g_tokcnt[NTOK];
__device__ __align__(128) int   g_toklist[NTOK * 8];             // (e*CAP+slot) refs
__device__ __align__(128) __half g_xh [(size_t)NTOK * DDIM];
__device__ __align__(128) __half g_w1h[(size_t)NEXP * FDIM * DDIM]; // W1^T [E][F][D]
__device__ __align__(128) __half g_w2h[(size_t)NEXP * DDIM * FDIM]; // W2^T [E][D][F]
__device__ __align__(128) __half g_hh [(size_t)NEXP * CAP * FDIM];  // h [E][C][F]
__device__ __align__(128) float g_oute[(size_t)NEXP * CAP * DDIM];  // weighted expert out

// ---------------- small helpers ---------------------------------------------
__device__ __forceinline__ unsigned f2k(float f) {
    unsigned u = __float_as_uint(f);
    return u ^ ((u & 0x80000000u) ? 0xFFFFFFFFu : 0x80000000u);
}
__device__ __forceinline__ float gelu_exact(float v) {
    return 0.5f * v * (1.0f + erff(v * 0.70710678118654752440f));
}
__device__ __forceinline__ uint32_t cvta_smem(const void* p) {
    uint32_t a;
    asm("{ .reg .u64 t; cvta.to.shared.u64 t, %1; cvt.u32.u64 %0, t; }" : "=r"(a) : "l"(p));
    return a;
}
// swizzle for 64-byte rows: XOR 16B-col index (bits 5:4) with row bits (o bits 8:7)
__device__ __forceinline__ uint32_t swz64(uint32_t o) { return o ^ ((o >> 3) & 0x30); }
__device__ __forceinline__ uint32_t packh(__half a, __half b) {
    return (uint32_t)__half_as_ushort(a) | ((uint32_t)__half_as_ushort(b) << 16);
}

#define CP16(dst, src) asm volatile("cp.async.cg.shared.global [%0], [%1], 16;" :: "r"(dst), "l"(src))
#define CP_COMMIT()    asm volatile("cp.async.commit_group;" ::: "memory")
#define CP_WAIT(n)     asm volatile("cp.async.wait_group %0;" :: "n"(n) : "memory")

__device__ __forceinline__ void ldsm4(uint32_t* r, uint32_t addr) {
    asm volatile("ldmatrix.sync.aligned.m8n8.x4.shared.b16 {%0,%1,%2,%3}, [%4];"
                 : "=r"(r[0]), "=r"(r[1]), "=r"(r[2]), "=r"(r[3]) : "r"(addr));
}
__device__ __forceinline__ void mma16816(float* c, const uint32_t* a, const uint32_t* b) {
    asm volatile(
        "mma.sync.aligned.m16n8k16.row.col.f32.f16.f16.f32 "
        "{%0,%1,%2,%3}, {%4,%5,%6,%7}, {%8,%9}, {%0,%1,%2,%3};"
        : "+f"(c[0]), "+f"(c[1]), "+f"(c[2]), "+f"(c[3])
        : "r"(a[0]), "r"(a[1]), "r"(a[2]), "r"(a[3]), "r"(b[0]), "r"(b[1]));
}

// ---------------- K1: fused x->fp16 convert + router logits -----------------
// Block: 256 threads, 32 tokens. lane = token; warp w owns dims [w*64, w*64+64).
__global__ __launch_bounds__(256, 2) void k_xprep(const float* __restrict__ x,
                                                  const float* __restrict__ Wr)
{
    extern __shared__ __align__(16) float dynf[];
    float* sx = dynf;                         // [32][516]
    float* sW = dynf + 32 * 516;              // [8][512]
    float* sp = sW + NEXP * 512;              // [256][8]

    const int tid = threadIdx.x, warp = tid >> 5, lane = tid & 31;
    const int t0 = blockIdx.x * 32;

    if (tid < 32) g_tokcnt[t0 + tid] = 0;
    for (int i = tid; i < 4096; i += 256) {   // W: [d][e] -> sW[e][d]
        int d = i >> 3, e = i & 7;
        sW[e * 512 + d] = Wr[d * NEXP + e];
    }
    for (int i = tid; i < 4096; i += 256) {   // 32 tok x 128 float4
        int tok = i >> 7, dd = (i & 127) * 4;
        float4 v = *(const float4*)(x + (size_t)(t0 + tok) * DDIM + dd);
        *(float4*)&sx[tok * 516 + dd] = v;
        uint2 p;
        p.x = packh(__float2half(v.x), __float2half(v.y));
        p.y = packh(__float2half(v.z), __float2half(v.w));
        ((uint2*)g_xh)[((size_t)(t0 + tok) * DDIM + dd) >> 2] = p;
    }
    __syncthreads();

    float acc[NEXP] = {};
    const int d0 = warp * 64;
#pragma unroll
    for (int i = 0; i < 16; i++) {
        float4 xv = *(const float4*)&sx[lane * 516 + d0 + i * 4];
#pragma unroll
        for (int e = 0; e < NEXP; e++) {
            float4 w = *(const float4*)&sW[e * 512 + d0 + i * 4];  // broadcast
            acc[e] += xv.x * w.x + xv.y * w.y + xv.z * w.z + xv.w * w.w;
        }
    }
#pragma unroll
    for (int e = 0; e < NEXP; e++)
        sp[(warp * 32 + lane) * NEXP + e] = acc[e];
    __syncthreads();

    int tok = tid >> 3, e = tid & 7;
    float s = 0.f;
#pragma unroll
    for (int w = 0; w < 8; w++) s += sp[(w * 32 + tok) * NEXP + e];
    g_logitsT[e * NTOK + t0 + tok] = s;
}

// ---------------- K2: partial column max + sum(exp) (online softmax) --------
__global__ void k_colstats_part()
{
    int e = blockIdx.y, part = blockIdx.x;
    const float* col = g_logitsT + e * NTOK + part * (NTOK / NPART);
    __shared__ float rmax[512], rsum[512];
    int tid = threadIdx.x;
    float mx = -INFINITY;
    for (int n = tid; n < NTOK / NPART; n += 512) mx = fmaxf(mx, col[n]);
    rmax[tid] = mx; __syncthreads();
    for (int s = 256; s > 0; s >>= 1) {
        if (tid < s) rmax[tid] = fmaxf(rmax[tid], rmax[tid + s]);
        __syncthreads();
    }
    mx = rmax[0];
    float sm = 0.f;
    for (int n = tid; n < NTOK / NPART; n += 512) sm += expf(col[n] - mx);
    rsum[tid] = sm; __syncthreads();
    for (int s = 256; s > 0; s >>= 1) {
        if (tid < s) rsum[tid] += rsum[tid + s];
        __syncthreads();
    }
    if (tid == 0) { g_pmax[e * NPART + part] = mx; g_psum[e * NPART + part] = rsum[0]; }
}

// ---------------- K3: per-expert exact top-CAP via 8-bit histogram radix ----
__global__ void k_select()
{
    int e = blockIdx.x;
    const float* col = g_logitsT + e * NTOK;
    __shared__ int s_hist[256];
    __shared__ unsigned s_prefix;
    __shared__ int s_need, s_pos;
    __shared__ float s_mx, s_sm;
    __shared__ int s_eq[1024];
    int tid = threadIdx.x;
    if (tid == 0) {
        s_prefix = 0u; s_need = CAP; s_pos = 0;
        float mx = -INFINITY;
#pragma unroll
        for (int p = 0; p < NPART; p++) mx = fmaxf(mx, g_pmax[e * NPART + p]);
        float sm = 0.f;
#pragma unroll
        for (int p = 0; p < NPART; p++)
            sm += g_psum[e * NPART + p] * expf(g_pmax[e * NPART + p] - mx);
        s_mx = mx; s_sm = sm;
    }

#pragma unroll
    for (int shift = 24; shift >= 0; shift -= 8) {
        if (tid < 256) s_hist[tid] = 0;
        __syncthreads();
        unsigned pref = s_prefix;
        unsigned maskH = (shift == 24) ? 0u : (0xFFFFFFFFu << (shift + 8));
        for (int n = tid; n < NTOK; n += 1024) {
            unsigned k = f2k(col[n]);
            if ((k & maskH) == pref)
                atomicAdd(&s_hist[(k >> shift) & 255], 1);
        }
        __syncthreads();
        if (tid == 0) {
            int need = s_need, cum = 0, b = 255;
            for (; b > 0; b--) { cum += s_hist[b]; if (cum >= need) break; }
            if (cum < need) cum += s_hist[0];
            s_need = need - (cum - s_hist[b]);
            s_prefix = pref | ((unsigned)b << shift);
        }
        __syncthreads();
    }
    unsigned thr = s_prefix;
    int needEq = s_need;
    float mx = s_mx, sm = s_sm;

    for (int n = tid; n < NTOK; n += 1024) {
        float lv = col[n];
        if (f2k(lv) > thr) {
            int slot = atomicAdd(&s_pos, 1);
            g_idx [e * CAP + slot] = n;
            g_vals[e * CAP + slot] = expf(lv - mx) / sm;
            int p = atomicAdd(&g_tokcnt[n], 1);
            g_toklist[n * 8 + p] = e * CAP + slot;
        }
    }
    __syncthreads();
    int G = s_pos;

    int n0 = tid * (NTOK / 1024);
    int cntEq = 0;
    for (int n = n0; n < n0 + NTOK / 1024; n++) cntEq += (f2k(col[n]) == thr);
    s_eq[tid] = cntEq;
    __syncthreads();
    for (int off = 1; off < 1024; off <<= 1) {
        int v = (tid >= off) ? s_eq[tid - off] : 0;
        __syncthreads();
        s_eq[tid] += v;
        __syncthreads();
    }
    int rank = s_eq[tid] - cntEq;
    for (int n = n0; n < n0 + NTOK / 1024; n++) {
        if (f2k(col[n]) == thr) {
            if (rank < needEq) {
                int slot = G + rank;
                g_idx [e * CAP + slot] = n;
                g_vals[e * CAP + slot] = expf(col[n] - mx) / sm;
                int p = atomicAdd(&g_tokcnt[n], 1);
                g_toklist[n * 8 + p] = e * CAP + slot;
            }
            rank++;
        }
    }
}

// ---------------- weight converts (transpose to K-major fp16) ---------------
__global__ void k_cvt_w1(const float* __restrict__ W1)
{
    __shared__ float t[32][33];
    const int R = DDIM, C = FDIM;
    int e = blockIdx.z;
    const float* S = W1 + (size_t)e * R * C;
    int c0 = blockIdx.x * 32, r0 = blockIdx.y * 32;
    int tx = threadIdx.x, ty = threadIdx.y;
#pragma unroll
    for (int i = 0; i < 4; i++)
        t[ty + 8 * i][tx] = S[(size_t)(r0 + ty + 8 * i) * C + c0 + tx];
    __syncthreads();
#pragma unroll
    for (int i = 0; i < 4; i++) {
        float v = t[tx][ty + 8 * i];
        size_t o = (size_t)e * C * R + (size_t)(c0 + ty + 8 * i) * R + r0 + tx;
        g_w1h[o] = __float2half(v);
    }
}

__global__ void k_cvt_w2(const float* __restrict__ W2)
{
    __shared__ float t[32][33];
    const int R = FDIM, C = DDIM;
    int e = blockIdx.z;
    const float* S = W2 + (size_t)e * R * C;
    int c0 = blockIdx.x * 32, r0 = blockIdx.y * 32;
    int tx = threadIdx.x, ty = threadIdx.y;
#pragma unroll
    for (int i = 0; i < 4; i++)
        t[ty + 8 * i][tx] = S[(size_t)(r0 + ty + 8 * i) * C + c0 + tx];
    __syncthreads();
#pragma unroll
    for (int i = 0; i < 4; i++) {
        float v = t[tx][ty + 8 * i];
        size_t o = (size_t)e * C * R + (size_t)(c0 + ty + 8 * i) * R + r0 + tx;
        g_w2h[o] = __float2half(v);
    }
}

// ================== mma.sync GEMM mainloop helpers (R5 proven) ==============
struct FragState {
    uint32_t aoff[2][2];   // [mfrag][kk]
    uint32_t boff[4][2];   // [nf2][kk]
};
__device__ __forceinline__ void frag_offsets(FragState& fs, int lane, int mwarp, int nwarp)
{
    int r16 = lane & 15, hi16 = (lane >> 4) * 16;
#pragma unroll
    for (int mf = 0; mf < 2; mf++)
#pragma unroll
        for (int kk = 0; kk < 2; kk++)
            fs.aoff[mf][kk] = swz64((uint32_t)((mwarp * 32 + mf * 16 + r16) * 64 + kk * 32 + hi16));
#pragma unroll
    for (int nf2 = 0; nf2 < 4; nf2++)
#pragma unroll
        for (int kk = 0; kk < 2; kk++)
            fs.boff[nf2][kk] = swz64((uint32_t)((nwarp * 64 + nf2 * 16 + r16) * 64 + kk * 32 + hi16));
}

__device__ __forceinline__ void compute_stage(float c[2][8][4], const FragState& fs,
                                              uint32_t abase)
{
    const uint32_t bbase = abase + 8192;
#pragma unroll
    for (int kk = 0; kk < 2; kk++) {
        uint32_t a[2][4], b[8][2];
#pragma unroll
        for (int mf = 0; mf < 2; mf++)
            ldsm4(a[mf], abase + fs.aoff[mf][kk]);
#pragma unroll
        for (int nf2 = 0; nf2 < 4; nf2++) {
            uint32_t r[4];
            ldsm4(r, bbase + fs.boff[nf2][kk]);
            b[2 * nf2][0] = r[0]; b[2 * nf2][1] = r[2];
            b[2 * nf2 + 1][0] = r[1]; b[2 * nf2 + 1][1] = r[3];
        }
#pragma unroll
        for (int mf = 0; mf < 2; mf++)
#pragma unroll
            for (int nf = 0; nf < 8; nf++)
                mma16816(c[mf][nf], a[mf], b[nf]);
    }
}

// ---------------- GEMM1: h = gelu(gather(x) @ W1 + b1) ----------------------
__device__ __forceinline__ void g1_load(int tid, const int* s_tok, int e, int bn0,
                                        uint32_t dynb, int kt, int st)
{
    int k0 = kt * BK;
    uint32_t base = dynb + st * STAGE_BYTES;
#pragma unroll
    for (int t = tid; t < 512; t += 256) {
        int row = t >> 2, cc = t & 3;
        uint32_t o = swz64((uint32_t)(row * 64 + cc * 16));
        size_t ga = (size_t)s_tok[row] * DDIM + k0 + cc * 8;
        CP16(base + o, g_xh + ga);
        size_t gb = (size_t)(e * FDIM + bn0 + row) * DDIM + k0 + cc * 8;
        CP16(base + 8192 + o, g_w1h + gb);
    }
}

__global__ __launch_bounds__(256, 2) void k_gemm1_mma(const float* __restrict__ b1)
{
    extern __shared__ __align__(16) unsigned char dynraw[];
    __shared__ int s_tok[BM];
    __shared__ float s_bias[BN];

    const int tid = threadIdx.x, wid = tid >> 5, lane = tid & 31;
    const int mwarp = wid & 3, nwarp = wid >> 2;
    const int e = blockIdx.z, bn0 = blockIdx.x * BN, bm0 = blockIdx.y * BM;

    uint32_t rawb = cvta_smem(dynraw);
    uint32_t pad = (1024u - (rawb & 1023u)) & 1023u;
    uint32_t dynb = rawb + pad;
    unsigned char* dynp = dynraw + pad;

    if (tid < BM) s_tok[tid] = g_idx[e * CAP + bm0 + tid];
    if (tid < BN) s_bias[tid] = b1[e * FDIM + bn0 + tid];
    __syncthreads();

    FragState fs;
    frag_offsets(fs, lane, mwarp, nwarp);
    float c[2][8][4] = {};

    const int KT = DDIM / BK;  // 16
    g1_load(tid, s_tok, e, bn0, dynb, 0, 0); CP_COMMIT();
    g1_load(tid, s_tok, e, bn0, dynb, 1, 1); CP_COMMIT();
    g1_load(tid, s_tok, e, bn0, dynb, 2, 2); CP_COMMIT();

    for (int kt = 0; kt < KT; kt++) {
        CP_WAIT(2);
        __syncthreads();
        if (kt + STAGES - 1 < KT)
            g1_load(tid, s_tok, e, bn0, dynb, kt + STAGES - 1, (kt + STAGES - 1) & 3);
        CP_COMMIT();
        compute_stage(c, fs, dynb + (kt & 3) * STAGE_BYTES);
    }
    __syncthreads();   // all warps done with stages before epilogue reuses smem

    // epilogue: gelu -> fp16 -> smem stage -> coalesced 16B stores
#pragma unroll
    for (int mf = 0; mf < 2; mf++)
#pragma unroll
        for (int nf = 0; nf < 8; nf++)
#pragma unroll
            for (int half = 0; half < 2; half++) {
                int row = mwarp * 32 + mf * 16 + (lane >> 2) + half * 8;
                int col = nwarp * 64 + nf * 8 + (lane & 3) * 2;
                float v0 = c[mf][nf][half * 2 + 0] + s_bias[col];
                float v1 = c[mf][nf][half * 2 + 1] + s_bias[col + 1];
                uint32_t off = (uint32_t)row * 256 + (((uint32_t)col * 2) ^ (((uint32_t)row & 15) << 4));
                *(uint32_t*)(dynp + off) =
                    packh(__float2half(gelu_exact(v0)), __float2half(gelu_exact(v1)));
            }
    __syncthreads();
#pragma unroll
    for (int it = 0; it < 8; it++) {
        int g = tid + it * 256;                  // 2048 16B chunks
        int r2 = g >> 4, seg = g & 15;
        uint32_t off = (uint32_t)r2 * 256 + (((uint32_t)seg * 16) ^ (((uint32_t)r2 & 15) << 4));
        uint4 vh = *(const uint4*)(dynp + off);
        size_t hb = ((size_t)(e * CAP + bm0 + r2)) * FDIM + bn0;
        *(uint4*)((char*)g_hh + hb * 2 + seg * 16) = vh;
    }
}

// ---------------- GEMM2: oute = (h @ W2 + b2) * vals ------------------------
__device__ __forceinline__ void g2_load(int tid, int e, int bn0, int bm0,
                                        uint32_t dynb, int kt, int st)
{
    int k0 = kt * BK;
    uint32_t base = dynb + st * STAGE_BYTES;
#pragma unroll
    for (int t = tid; t < 512; t += 256) {
        int row = t >> 2, cc = t & 3;
        uint32_t o = swz64((uint32_t)(row * 64 + cc * 16));
        size_t ga = (size_t)(e * CAP + bm0 + row) * FDIM + k0 + cc * 8;
        CP16(base + o, g_hh + ga);
        size_t gb = (size_t)(e * DDIM + bn0 + row) * FDIM + k0 + cc * 8;
        CP16(base + 8192 + o, g_w2h + gb);
    }
}

__global__ __launch_bounds__(256, 2) void k_gemm2_mma(const float* __restrict__ b2)
{
    extern __shared__ __align__(16) unsigned char dynraw[];
    __shared__ float s_val[BM];
    __shared__ float s_bias[BN];

    const int tid = threadIdx.x, wid = tid >> 5, lane = tid & 31;
    const int mwarp = wid & 3, nwarp = wid >> 2;
    const int e = blockIdx.z, bn0 = blockIdx.x * BN, bm0 = blockIdx.y * BM;

    uint32_t rawb = cvta_smem(dynraw);
    uint32_t pad = (1024u - (rawb & 1023u)) & 1023u;
    uint32_t dynb = rawb + pad;
    unsigned char* dynp = dynraw + pad;

    if (tid < BM) s_val[tid] = g_vals[e * CAP + bm0 + tid];
    if (tid < BN) s_bias[tid] = b2[e * DDIM + bn0 + tid];
    __syncthreads();

    FragState fs;
    frag_offsets(fs, lane, mwarp, nwarp);
    float c[2][8][4] = {};

    const int KT = FDIM / BK;  // 64
    g2_load(tid, e, bn0, bm0, dynb, 0, 0); CP_COMMIT();
    g2_load(tid, e, bn0, bm0, dynb, 1, 1); CP_COMMIT();
    g2_load(tid, e, bn0, bm0, dynb, 2, 2); CP_COMMIT();

    for (int kt = 0; kt < KT; kt++) {
        CP_WAIT(2);
        __syncthreads();
        if (kt + STAGES - 1 < KT)
            g2_load(tid, e, bn0, bm0, dynb, kt + STAGES - 1, (kt + STAGES - 1) & 3);
        CP_COMMIT();
        compute_stage(c, fs, dynb + (kt & 3) * STAGE_BYTES);
    }
    __syncthreads();

    // epilogue: (acc + b2) * val -> f32 smem stage (512B/row) -> 16B stores
#pragma unroll
    for (int mf = 0; mf < 2; mf++)
#pragma unroll
        for (int nf = 0; nf < 8; nf++)
#pragma unroll
            for (int half = 0; half < 2; half++) {
                int row = mwarp * 32 + mf * 16 + (lane >> 2) + half * 8;
                int col = nwarp * 64 + nf * 8 + (lane & 3) * 2;
                float vr = s_val[row];
                float2 o2;
                o2.x = (c[mf][nf][half * 2 + 0] + s_bias[col]) * vr;
                o2.y = (c[mf][nf][half * 2 + 1] + s_bias[col + 1]) * vr;
                uint32_t off = (uint32_t)row * 512 + (((uint32_t)col * 4) ^ (((uint32_t)row & 31) << 4));
                *(float2*)(dynp + off) = o2;
            }
    __syncthreads();
#pragma unroll
    for (int it = 0; it < 16; it++) {
        int g = tid + it * 256;                  // 4096 16B chunks
        int r2 = g >> 5, seg = g & 31;
        uint32_t off = (uint32_t)r2 * 512 + (((uint32_t)seg * 16) ^ (((uint32_t)r2 & 31) << 4));
        uint4 v = *(const uint4*)(dynp + off);
        size_t ob = ((size_t)(e * CAP + bm0 + r2)) * DDIM + bn0;
        *(uint4*)((char*)g_oute + ob * 4 + seg * 16) = v;
    }
}

// ---------------- K6: gather-reduce scatter to output -----------------------
__global__ void k_scatter(float* __restrict__ out)
{
    int t = blockIdx.x * 2 + (threadIdx.x >> 7);
    int l = threadIdx.x & 127;
    int cnt = g_tokcnt[t];
    float4 acc = make_float4(0.f, 0.f, 0.f, 0.f);
    for (int i = 0; i < cnt; i++) {
        int ref = g_toklist[t * 8 + i];
        float4 v = ((const float4*)(g_oute + (size_t)ref * DDIM))[l];
        acc.x += v.x; acc.y += v.y; acc.z += v.z; acc.w += v.w;
    }
    ((float4*)out)[(size_t)t * (DDIM / 4) + l] = acc;
}

// ---------------------------------------------------------------------------
extern "C" void kernel_launch(void* const* d_in, const int* in_sizes, int n_in,
                              void* d_out, int out_size)
{
    const float* x  = (const float*)d_in[0];
    const float* Wr = (const float*)d_in[1];
    const float* W1 = (const float*)d_in[2];
    const float* b1 = (const float*)d_in[3];
    const float* W2 = (const float*)d_in[4];
    const float* b2 = (const float*)d_in[5];
    float* out = (float*)d_out;

    cudaFuncSetAttribute(k_xprep, cudaFuncAttributeMaxDynamicSharedMemorySize, XPREP_SMEM);
    cudaFuncSetAttribute(k_gemm1_mma, cudaFuncAttributeMaxDynamicSharedMemorySize, DYN_SMEM);
    cudaFuncSetAttribute(k_gemm2_mma, cudaFuncAttributeMaxDynamicSharedMemorySize, DYN_SMEM);

    k_xprep   <<<NTOK / 32, 256, XPREP_SMEM>>>(x, Wr);
    k_cvt_w1  <<<dim3(FDIM / 32, DDIM / 32, NEXP), dim3(32, 8)>>>(W1);
    k_cvt_w2  <<<dim3(DDIM / 32, FDIM / 32, NEXP), dim3(32, 8)>>>(W2);
    k_colstats_part<<<dim3(NPART, NEXP), 512>>>();
    k_select  <<<NEXP, 1024>>>();
    k_gemm1_mma<<<dim3(FDIM / BN, CAP / BM, NEXP), 256, DYN_SMEM>>>(b1);
    k_gemm2_mma<<<dim3(DDIM / BN, CAP / BM, NEXP), 256, DYN_SMEM>>>(b2);
    k_scatter <<<NTOK / 2, 256>>>(out);
}